// round 16
// baseline (speedup 1.0000x reference)
#include <cuda_runtime.h>
#include <cuda_bf16.h>
#include <cuda_fp16.h>
#include <math.h>
#include <stdint.h>

#define NN 100000
#define EE 1600000
#define EPSV 1e-5f
#define LOSCALE 2048.0f
#define INV_LOSCALE (1.0f / 2048.0f)

// ================= device scratch =================
__device__ __half g_actF[(size_t)NN * 256];          // activation fp16, row stride KP
__device__ __half g_bufH[(size_t)NN * 224];          // GEMM output fp16 (layers 1-5), tight stride
__device__ float  g_bufA[(size_t)NN * 20];           // GEMM output fp32 (layer 6), stride 20
__device__ __half g_hB[57344];                       // W^T fp16 hi, [Npad, KP]
__device__ __half g_lB[57344];                       // W^T fp16 lo (scaled by 2048)
__device__ int   g_deg[NN];
__device__ float g_dis[NN];
__device__ int   g_rowptr[NN + 1];
__device__ int   g_cursor[NN];
__device__ int   g_blocksum[256];
__device__ int   g_blockoff[256];
__device__ int   g_src[EE];
__device__ float g_w[EE];
__device__ float g_sumsA[5][256];    // per-layer BN stats
__device__ float g_sumsqA[5][256];
__device__ float g_cvec[256];

__device__ __forceinline__ uint32_t smem_u32(const void* p) {
    uint32_t a;
    asm("{ .reg .u64 t; cvta.to.shared.u64 t, %1; cvt.u32.u64 %0, t; }" : "=r"(a) : "l"(p));
    return a;
}

// ================= preprocessing =================
__global__ void k_zero() {
    int i = blockIdx.x * blockDim.x + threadIdx.x;
    if (i < NN) g_deg[i] = 0;
    if (i < 5 * 256) {
        ((float*)g_sumsA)[i]  = 0.f;
        ((float*)g_sumsqA)[i] = 0.f;
    }
}
__global__ void k_hist(const int* __restrict__ dst) {
    int e = blockIdx.x * blockDim.x + threadIdx.x;
    if (e < EE) atomicAdd(&g_deg[dst[e]], 1);
}
__global__ void k_scan1() {
    __shared__ int sh[512];
    int i = blockIdx.x * 512 + threadIdx.x;
    int v = 0;
    if (i < NN) {
        v = g_deg[i];
        g_dis[i] = rsqrtf((float)(v + 1));   // self loop included
    }
    sh[threadIdx.x] = v;
    __syncthreads();
    #pragma unroll
    for (int off = 1; off < 512; off <<= 1) {
        int t = (threadIdx.x >= off) ? sh[threadIdx.x - off] : 0;
        __syncthreads();
        sh[threadIdx.x] += t;
        __syncthreads();
    }
    if (i < NN) g_rowptr[i] = sh[threadIdx.x] - v;
    if (threadIdx.x == 511) g_blocksum[blockIdx.x] = sh[511];
}
__global__ void k_scan2(int nb) {
    __shared__ int sh[256];
    int v = (threadIdx.x < nb) ? g_blocksum[threadIdx.x] : 0;
    sh[threadIdx.x] = v;
    __syncthreads();
    #pragma unroll
    for (int off = 1; off < 256; off <<= 1) {
        int t = (threadIdx.x >= off) ? sh[threadIdx.x - off] : 0;
        __syncthreads();
        sh[threadIdx.x] += t;
        __syncthreads();
    }
    if (threadIdx.x < nb) g_blockoff[threadIdx.x] = sh[threadIdx.x] - v;
}
__global__ void k_scan3() {
    int i = blockIdx.x * 512 + threadIdx.x;
    if (i < NN) {
        int r = g_rowptr[i] + g_blockoff[blockIdx.x];
        g_rowptr[i] = r;
        g_cursor[i] = r;
    }
    if (i == 0 && blockIdx.x == 0) g_rowptr[NN] = EE;
}
__global__ void k_fill(const int* __restrict__ ei) {
    int e = blockIdx.x * blockDim.x + threadIdx.x;
    if (e < EE) {
        int s  = ei[e];
        int dv = ei[EE + e];
        float w = g_dis[s] * g_dis[dv];
        int p = atomicAdd(&g_cursor[dv], 1);
        g_src[p] = s;
        g_w[p]   = w;
    }
}

// ================= conversions / merged per-layer prep =================
__global__ void k_convX(const float* __restrict__ x) {
    int idx = blockIdx.x * blockDim.x + threadIdx.x;
    if (idx >= NN * 32) return;
    int i = idx >> 5, g = idx & 31;
    int k0 = g * 8;
    __half h[8];
    #pragma unroll
    for (int q = 0; q < 8; q++) {
        int k = k0 + q;
        float v = (k < 220) ? x[(size_t)i * 220 + k] : 0.f;
        h[q] = __float2half_rn(v);
    }
    *(uint4*)(g_actF + (size_t)i * 256 + k0) = *(uint4*)h;
}

__global__ void __launch_bounds__(256) k_prepLayer(
    const float* __restrict__ W, const float* __restrict__ gg, const float* __restrict__ bb,
    int K_, int N_, int KP, int useScale, int statIdx)
{
    __shared__ float s_scale[256], s_shift[256], s_red[256];
    int t = threadIdx.x;
    int n = blockIdx.x;

    float sc = 1.f, sh = 0.f;
    if (useScale && t < K_) {
        float m   = g_sumsA[statIdx][t] * (1.f / NN);
        float var = g_sumsqA[statIdx][t] * (1.f / NN) - m * m;
        float rs  = rsqrtf(var + EPSV);
        sc = rs * gg[t];
        sh = bb[t] - m * sc;
    }
    s_scale[t] = sc;
    s_shift[t] = sh;
    __syncthreads();

    for (int k = t; k < KP; k += 256) {
        float v = 0.f;
        if (n < N_ && k < K_) v = W[(size_t)k * N_ + n] * s_scale[k];
        __half hv = __float2half_rn(v);
        g_hB[(size_t)n * KP + k] = hv;
        g_lB[(size_t)n * KP + k] = __float2half_rn((v - __half2float(hv)) * LOSCALE);
    }

    if (useScale) {
        float part = 0.f;
        if (n < N_)
            for (int k = t; k < K_; k += 256) part += s_shift[k] * W[(size_t)k * N_ + n];
        s_red[t] = part;
        __syncthreads();
        #pragma unroll
        for (int off = 128; off > 0; off >>= 1) {
            if (t < off) s_red[t] += s_red[t + off];
            __syncthreads();
        }
        if (t == 0) g_cvec[n] = s_red[0];
    }
}

// ================= HMMA fp16 2-term split GEMM (A register double-buffer) ========
__device__ __forceinline__ void ldsm4(uint32_t& r0, uint32_t& r1, uint32_t& r2, uint32_t& r3,
                                      uint32_t addr) {
    asm volatile("ldmatrix.sync.aligned.m8n8.x4.shared.b16 {%0,%1,%2,%3}, [%4];"
        : "=r"(r0), "=r"(r1), "=r"(r2), "=r"(r3) : "r"(addr));
}
__device__ __forceinline__ void mma16816f(float* d, uint32_t a0, uint32_t a1, uint32_t a2,
                                          uint32_t a3, uint32_t b0, uint32_t b1) {
    asm volatile(
        "mma.sync.aligned.m16n8k16.row.col.f32.f16.f16.f32 "
        "{%0,%1,%2,%3}, {%4,%5,%6,%7}, {%8,%9}, {%0,%1,%2,%3};"
        : "+f"(d[0]), "+f"(d[1]), "+f"(d[2]), "+f"(d[3])
        : "r"(a0), "r"(a1), "r"(a2), "r"(a3), "r"(b0), "r"(b1));
}
#define SWZ(r, q) (((uint32_t)(r) << 7) + ((((uint32_t)(q)) ^ ((uint32_t)(r) & 7)) << 4))

template <int JM8>
__global__ void __launch_bounds__(256, 2) k_hgemm(int KP, int strideOut, int useCvec,
                                                  int colOff, int outHalf) {
    constexpr int TMAX  = JM8 / 2;
    constexpr int BROWS = JM8 * 8;
    __shared__ __half sA[128 * 64];
    __shared__ __half sBh[64 * 64];
    __shared__ __half sBl[64 * 64];

    int tid = threadIdx.x;
    int warp = tid >> 5, lane = tid & 31;
    int rowbase = blockIdx.y * 128;
    int colbase = colOff + blockIdx.x * 64;

    float accH[JM8][4], accL[JM8][4];
    #pragma unroll
    for (int j = 0; j < JM8; j++)
        #pragma unroll
        for (int q = 0; q < 4; q++) { accH[j][q] = 0.f; accL[j][q] = 0.f; }

    uint32_t sAB = smem_u32(sA);
    uint32_t sBhB = smem_u32(sBh), sBlB = smem_u32(sBl);

    int arow = warp * 16 + (lane & 15);
    int achk = lane >> 4;
    int brow = (lane & 7) + ((lane >> 4) << 3);
    int bchk = (lane >> 3) & 1;

    // this thread's A-load coordinates (4 rows, 1 quad each)
    int aR[4], aQ;
    {
        int u0 = tid;
        aQ = u0 & 7;
        #pragma unroll
        for (int it = 0; it < 4; it++) aR[it] = (tid + it * 256) >> 3;
    }
    bool rowOK[4];
    #pragma unroll
    for (int it = 0; it < 4; it++) rowOK[it] = (rowbase + aR[it]) < NN;

    int nchunks = KP >> 6;

    // prefetch A chunk 0 into registers
    uint4 aReg[4];
    #pragma unroll
    for (int it = 0; it < 4; it++)
        aReg[it] = rowOK[it]
            ? *(const uint4*)(g_actF + (size_t)(rowbase + aR[it]) * KP + 0 + aQ * 8)
            : make_uint4(0u, 0u, 0u, 0u);

    for (int c = 0; c < nchunks; c++) {
        int k0 = c << 6;
        // store prefetched A regs to smem
        #pragma unroll
        for (int it = 0; it < 4; it++)
            *(uint4*)((char*)sA + SWZ(aR[it], aQ)) = aReg[it];
        // B tiles for this chunk (sync path; B is small + L2-hot)
        #pragma unroll
        for (int it = 0; it < BROWS / 32; it++) {
            int u = tid + it * 256;
            int n = u >> 3, q = u & 7;
            size_t off = (size_t)(colbase + n) * KP + k0 + q * 8;
            uint32_t dz = SWZ(n, q);
            *(uint4*)((char*)sBh + dz) = *(const uint4*)(g_hB + off);
            *(uint4*)((char*)sBl + dz) = *(const uint4*)(g_lB + off);
        }
        __syncthreads();

        // issue next chunk's A loads early (overlap with MMA below)
        if (c + 1 < nchunks) {
            int k1 = (c + 1) << 6;
            #pragma unroll
            for (int it = 0; it < 4; it++)
                aReg[it] = rowOK[it]
                    ? *(const uint4*)(g_actF + (size_t)(rowbase + aR[it]) * KP + k1 + aQ * 8)
                    : make_uint4(0u, 0u, 0u, 0u);
        }

        #pragma unroll
        for (int s = 0; s < 4; s++) {
            int aq = s * 2 + achk;
            uint32_t ah0, ah1, ah2, ah3;
            ldsm4(ah0, ah1, ah2, ah3, sAB + SWZ(arow, aq));
            int bq = s * 2 + bchk;
            #pragma unroll
            for (int t = 0; t < TMAX; t++) {
                uint32_t bh[4], bl[4];
                uint32_t boff = SWZ(brow + t * 16, bq);
                ldsm4(bh[0], bh[1], bh[2], bh[3], sBhB + boff);
                ldsm4(bl[0], bl[1], bl[2], bl[3], sBlB + boff);
                #pragma unroll
                for (int jj = 0; jj < 2; jj++) {
                    int j = t * 2 + jj;
                    mma16816f(accH[j], ah0, ah1, ah2, ah3, bh[jj*2], bh[jj*2+1]);
                    mma16816f(accL[j], ah0, ah1, ah2, ah3, bl[jj*2], bl[jj*2+1]);
                }
            }
        }
        __syncthreads();
    }

    int r0 = rowbase + warp * 16 + (lane >> 2);
    int c00 = colbase + (lane & 3) * 2;
    #pragma unroll
    for (int j = 0; j < JM8; j++) {
        int col = c00 + j * 8;
        if (col >= strideOut) continue;
        float cv0 = useCvec ? g_cvec[col] : 0.f;
        float cv1 = useCvec ? g_cvec[col + 1] : 0.f;
        float v00 = accH[j][0] + accL[j][0] * INV_LOSCALE + cv0;
        float v01 = accH[j][1] + accL[j][1] * INV_LOSCALE + cv1;
        float v10 = accH[j][2] + accL[j][2] * INV_LOSCALE + cv0;
        float v11 = accH[j][3] + accL[j][3] * INV_LOSCALE + cv1;
        if (outHalf) {
            if (r0 < NN)
                *(__half2*)(g_bufH + (size_t)r0 * strideOut + col) = __floats2half2_rn(v00, v01);
            if (r0 + 8 < NN)
                *(__half2*)(g_bufH + (size_t)(r0 + 8) * strideOut + col) = __floats2half2_rn(v10, v11);
        } else {
            if (r0 < NN) {
                float* p = g_bufA + (size_t)r0 * strideOut + col;
                p[0] = v00; p[1] = v01;
            }
            if (r0 + 8 < NN) {
                float* p = g_bufA + (size_t)(r0 + 8) * strideOut + col;
                p[0] = v10; p[1] = v11;
            }
        }
    }
}

// ===== aggregation over fp16 h (layers 1-5): 2-deep gather prefetch (R13 proven) =====
template <int EPG>
__global__ void __launch_bounds__(256) k_aggH(const float* __restrict__ bias,
                                              int d, int s8, int KPn, int statIdx)
{
    constexpr int G = 32 / EPG;
    int lane = threadIdx.x & 31;
    int warp = threadIdx.x >> 5;
    int sub  = lane & (G - 1);
    int grp  = lane / G;

    __shared__ float sh_sum[256], sh_sq[256], sh_bias[256];
    if (threadIdx.x < 256) {
        sh_sum[threadIdx.x] = 0.f;
        sh_sq[threadIdx.x] = 0.f;
        sh_bias[threadIdx.x] = (threadIdx.x < d) ? bias[threadIdx.x] : 0.f;
    }
    __syncthreads();

    float st_s[8], st_q[8];
    #pragma unroll
    for (int i = 0; i < 8; i++) { st_s[i] = 0.f; st_q[i] = 0.f; }

    const float4* __restrict__ H8 = (const float4*)g_bufH;
    bool lactive = (sub < s8);
    int nsg = KPn >> 3;
    const uint4 Z4 = make_uint4(0u, 0u, 0u, 0u);

    for (int node = blockIdx.x * 8 + warp; node < NN; node += gridDim.x * 8) {
        float acc8[8];
        #pragma unroll
        for (int i = 0; i < 8; i++) acc8[i] = 0.f;

        float dn = g_dis[node];
        if (grp == 0 && lactive) {
            float sw = dn * dn;
            uint4 u = *(const uint4*)(H8 + (size_t)node * s8 + sub);
            const __half2* h2 = (const __half2*)&u;
            #pragma unroll
            for (int i = 0; i < 4; i++) {
                float2 t = __half22float2(h2[i]);
                acc8[2*i]   = sw * t.x;
                acc8[2*i+1] = sw * t.y;
            }
        }

        int start = g_rowptr[node], end = g_rowptr[node + 1];
        for (int base = start; base < end; base += 32) {
            int e = base + lane;
            int ssrc = 0; float ww = 0.f;
            if (e < end) { ssrc = g_src[e]; ww = g_w[e]; }
            int cnt = min(32, end - base);
            int steps = (cnt + EPG - 1) / EPG;

            int   s2 = __shfl_sync(0xffffffffu, ssrc, grp);
            float w2 = __shfl_sync(0xffffffffu, ww,  grp);
            bool  vld = (grp < cnt) && lactive;
            uint4 v = vld ? *(const uint4*)(H8 + (size_t)s2 * s8 + sub) : Z4;

            for (int t = 0; t < steps; t++) {
                int ein = (t + 1) * EPG + grp;
                int   s2n = __shfl_sync(0xffffffffu, ssrc, ein & 31);
                float w2n = __shfl_sync(0xffffffffu, ww,  ein & 31);
                bool  vldn = (ein < cnt) && lactive;
                uint4 vn = vldn ? *(const uint4*)(H8 + (size_t)s2n * s8 + sub) : Z4;

                const __half2* h2 = (const __half2*)&v;
                #pragma unroll
                for (int i = 0; i < 4; i++) {
                    float2 tt = __half22float2(h2[i]);
                    acc8[2*i]   += w2 * tt.x;
                    acc8[2*i+1] += w2 * tt.y;
                }
                v = vn; w2 = w2n;
            }
        }

        if (EPG > 1) {
            #pragma unroll
            for (int off = G; off < 32; off <<= 1) {
                #pragma unroll
                for (int i = 0; i < 8; i++)
                    acc8[i] += __shfl_xor_sync(0xffffffffu, acc8[i], off);
            }
        }

        if (grp == 0) {
            for (int g = sub; g < nsg; g += G) {
                bool own = (g == sub);
                uint4 pf;
                __half* fp = (__half*)&pf;
                #pragma unroll
                for (int i = 0; i < 8; i++) {
                    int col = g * 8 + i;
                    float v2 = 0.f;
                    if (own && col < d) {
                        v2 = fmaxf(acc8[i] + sh_bias[col], 0.f);
                        st_s[i] += v2;
                        st_q[i] += v2 * v2;
                    }
                    fp[i] = __float2half_rn(v2);
                }
                *(uint4*)(g_actF + (size_t)node * KPn + g * 8) = pf;
            }
        }
    }

    __syncthreads();
    if (grp == 0 && lactive) {
        #pragma unroll
        for (int i = 0; i < 8; i++) {
            int col = sub * 8 + i;
            if (col < d) {
                atomicAdd(&sh_sum[col], st_s[i]);
                atomicAdd(&sh_sq[col],  st_q[i]);
            }
        }
    }
    __syncthreads();
    if (threadIdx.x < d) {
        atomicAdd(&g_sumsA[statIdx][threadIdx.x],  sh_sum[threadIdx.x]);
        atomicAdd(&g_sumsqA[statIdx][threadIdx.x], sh_sq[threadIdx.x]);
    }
}

// ===== final aggregation (layer 6): fp32 gather with 2-deep prefetch, log_softmax =====
__global__ void __launch_bounds__(256) k_aggLast(const float* __restrict__ bias,
                                                 float* __restrict__ outp, int d, int s4)
{
    constexpr int EPG = 4, G = 8;
    int lane = threadIdx.x & 31;
    int warp = threadIdx.x >> 5;
    int sub  = lane & (G - 1);
    int grp  = lane / G;

    const float4* __restrict__ H = (const float4*)g_bufA;
    bool lactive = (sub < s4);
    const float4 ZF = make_float4(0.f, 0.f, 0.f, 0.f);

    for (int node = blockIdx.x * 8 + warp; node < NN; node += gridDim.x * 8) {
        float4 acc = ZF;
        float dn = g_dis[node];
        if (grp == 0 && lactive) {
            float sw = dn * dn;
            float4 h = H[(size_t)node * s4 + sub];
            acc.x = sw * h.x; acc.y = sw * h.y; acc.z = sw * h.z; acc.w = sw * h.w;
        }

        int start = g_rowptr[node], end = g_rowptr[node + 1];
        for (int base = start; base < end; base += 32) {
            int e = base + lane;
            int ssrc = 0; float ww = 0.f;
            if (e < end) { ssrc = g_src[e]; ww = g_w[e]; }
            int cnt = min(32, end - base);
            int steps = (cnt + EPG - 1) / EPG;

            int e0 = grp;
            int   s2a = __shfl_sync(0xffffffffu, ssrc, e0 & 31);
            float w2a = __shfl_sync(0xffffffffu, ww,  e0 & 31);
            float4 v0 = ((e0 < cnt) && lactive) ? H[(size_t)s2a * s4 + sub] : ZF;

            for (int t = 0; t < steps; t++) {
                int ein = (t + 1) * EPG + grp;
                int   s2n = __shfl_sync(0xffffffffu, ssrc, ein & 31);
                float w2n = __shfl_sync(0xffffffffu, ww,  ein & 31);
                float4 vn = ((ein < cnt) && lactive) ? H[(size_t)s2n * s4 + sub] : ZF;

                acc.x += w2a * v0.x; acc.y += w2a * v0.y;
                acc.z += w2a * v0.z; acc.w += w2a * v0.w;
                v0 = vn; w2a = w2n;
            }
        }

        #pragma unroll
        for (int off = G; off < 32; off <<= 1) {
            acc.x += __shfl_xor_sync(0xffffffffu, acc.x, off);
            acc.y += __shfl_xor_sync(0xffffffffu, acc.y, off);
            acc.z += __shfl_xor_sync(0xffffffffu, acc.z, off);
            acc.w += __shfl_xor_sync(0xffffffffu, acc.w, off);
        }

        float vals[4] = {acc.x, acc.y, acc.z, acc.w};
        float lmax = -INFINITY;
        #pragma unroll
        for (int q = 0; q < 4; q++) {
            int col = sub * 4 + q;
            float v = (grp == 0 && col < d) ? vals[q] + bias[col] : -INFINITY;
            vals[q] = v;
            lmax = fmaxf(lmax, v);
        }
        #pragma unroll
        for (int off = 1; off < G; off <<= 1)
            lmax = fmaxf(lmax, __shfl_xor_sync(0xffffffffu, lmax, off));
        float lsum = 0.f;
        #pragma unroll
        for (int q = 0; q < 4; q++) {
            int col = sub * 4 + q;
            if (grp == 0 && col < d) lsum += expf(vals[q] - lmax);
        }
        #pragma unroll
        for (int off = 1; off < G; off <<= 1)
            lsum += __shfl_xor_sync(0xffffffffu, lsum, off);
        float lse = logf(lsum) + lmax;
        if (grp == 0) {
            #pragma unroll
            for (int q = 0; q < 4; q++) {
                int col = sub * 4 + q;
                if (col < d) outp[(size_t)node * d + col] = vals[q] - lse;
            }
        }
    }
}

// ================= launch =================
extern "C" void kernel_launch(void* const* d_in, const int* in_sizes, int n_in,
                              void* d_out, int out_size) {
    const float* x  = (const float*)d_in[0];
    const int*   ei = (const int*)d_in[1];
    static const int DIMS_[7]  = {220, 220, 150, 100, 60, 30, 17};
    static const int KPt[6]    = {256, 256, 192, 128, 64, 64};
    static const int NPADc[6]  = {224, 160, 128, 64, 32, 32};
    static const int STRIDEo[6]= {224, 152, 104, 64, 32, 20};
    const float* W[6]; const float* b[6];
    for (int i = 0; i < 6; i++) {
        W[i] = (const float*)d_in[2 + 2 * i];
        b[i] = (const float*)d_in[3 + 2 * i];
    }
    const float* gpar[5]; const float* bpar[5];
    for (int i = 0; i < 5; i++) {
        gpar[i] = (const float*)d_in[14 + 2 * i];
        bpar[i] = (const float*)d_in[15 + 2 * i];
    }

    // preprocessing
    k_zero<<<(NN + 255) / 256, 256>>>();
    k_hist<<<(EE + 255) / 256, 256>>>(ei + EE);
    int nb = (NN + 511) / 512;
    k_scan1<<<nb, 512>>>();
    k_scan2<<<1, 256>>>(nb);
    k_scan3<<<nb, 512>>>();
    k_fill<<<(EE + 255) / 256, 256>>>(ei);
    k_convX<<<(NN * 32 + 255) / 256, 256>>>(x);

    const int AGG_GRID = 1184;
    const int ROW_BLKS = (NN + 127) / 128;

    for (int L = 0; L < 6; L++) {
        int K_ = DIMS_[L], Nc = DIMS_[L + 1];
        int KP = KPt[L], Npad = NPADc[L], so = STRIDEo[L];
        int outHalf = (L < 5) ? 1 : 0;
        int uc = L > 0 ? 1 : 0;

        k_prepLayer<<<Npad, 256>>>(W[L],
                                   L > 0 ? gpar[L - 1] : nullptr,
                                   L > 0 ? bpar[L - 1] : nullptr,
                                   K_, Nc, KP, uc, L > 0 ? L - 1 : 0);

        int nfull = Npad / 64;
        int tail  = Npad - nfull * 64;
        if (nfull > 0) {
            dim3 gg(nfull, ROW_BLKS);
            k_hgemm<8><<<gg, 256>>>(KP, so, uc, 0, outHalf);
        }
        if (tail > 0) {
            dim3 gg(1, ROW_BLKS);
            k_hgemm<4><<<gg, 256>>>(KP, so, uc, nfull * 64, outHalf);
        }

        if (L < 5) {
            int s8 = so / 8;                 // 28, 19, 13, 8, 4
            int KPn = KPt[L + 1];
            if (L <= 1)      k_aggH<1><<<AGG_GRID, 256>>>(b[L], Nc, s8, KPn, L);
            else if (L == 2) k_aggH<2><<<AGG_GRID, 256>>>(b[L], Nc, s8, KPn, L);
            else if (L == 3) k_aggH<4><<<AGG_GRID, 256>>>(b[L], Nc, s8, KPn, L);
            else             k_aggH<8><<<AGG_GRID, 256>>>(b[L], Nc, s8, KPn, L);
        } else {
            k_aggLast<<<AGG_GRID, 256>>>(b[L], (float*)d_out, Nc, so / 4);
        }
    }
}

// round 17
// speedup vs baseline: 1.0347x; 1.0347x over previous
#include <cuda_runtime.h>
#include <cuda_bf16.h>
#include <cuda_fp16.h>
#include <math.h>
#include <stdint.h>

#define NN 100000
#define EE 1600000
#define EPSV 1e-5f
#define LOSCALE 2048.0f
#define INV_LOSCALE (1.0f / 2048.0f)

// ================= device scratch =================
__device__ __half g_actF[(size_t)NN * 256];          // activation fp16, row stride KP
__device__ __half g_bufH[(size_t)NN * 224];          // GEMM output fp16 (layers 1-5), tight stride
__device__ float  g_bufA[(size_t)NN * 20];           // GEMM output fp32 (layer 6), stride 20
__device__ __half g_hB[57344];                       // W^T fp16 hi, [Npad, KP]
__device__ __half g_lB[57344];                       // W^T fp16 lo (scaled by 2048)
__device__ int   g_deg[NN];
__device__ float g_dis[NN];
__device__ int   g_rowptr[NN + 1];
__device__ int   g_cursor[NN];
__device__ int   g_blocksum[256];
__device__ int2  g_edge[EE];                         // {src, weight-bits} interleaved
__device__ float g_sumsA[5][256];    // per-layer BN stats
__device__ float g_sumsqA[5][256];
__device__ float g_cvec[256];

__device__ __forceinline__ uint32_t smem_u32(const void* p) {
    uint32_t a;
    asm("{ .reg .u64 t; cvta.to.shared.u64 t, %1; cvt.u32.u64 %0, t; }" : "=r"(a) : "l"(p));
    return a;
}

// ================= preprocessing =================
__global__ void k_zero() {
    int i = blockIdx.x * blockDim.x + threadIdx.x;
    if (i < NN) g_deg[i] = 0;
    if (i < 5 * 256) {
        ((float*)g_sumsA)[i]  = 0.f;
        ((float*)g_sumsqA)[i] = 0.f;
    }
}
__global__ void k_hist(const int* __restrict__ dst) {
    int e = blockIdx.x * blockDim.x + threadIdx.x;
    if (e < EE) atomicAdd(&g_deg[dst[e]], 1);
}
__global__ void k_scan1() {
    __shared__ int sh[512];
    int i = blockIdx.x * 512 + threadIdx.x;
    int v = 0;
    if (i < NN) {
        v = g_deg[i];
        g_dis[i] = rsqrtf((float)(v + 1));   // self loop included
    }
    sh[threadIdx.x] = v;
    __syncthreads();
    #pragma unroll
    for (int off = 1; off < 512; off <<= 1) {
        int t = (threadIdx.x >= off) ? sh[threadIdx.x - off] : 0;
        __syncthreads();
        sh[threadIdx.x] += t;
        __syncthreads();
    }
    if (i < NN) g_rowptr[i] = sh[threadIdx.x] - v;
    if (threadIdx.x == 511) g_blocksum[blockIdx.x] = sh[511];
}
// scan3 with inlined cross-block offset (replaces scan2+scan3)
__global__ void k_scan3() {
    __shared__ int soff;
    int i = blockIdx.x * 512 + threadIdx.x;
    if (threadIdx.x < 32) {
        int acc = 0;
        for (int b = threadIdx.x; b < blockIdx.x; b += 32) acc += g_blocksum[b];
        #pragma unroll
        for (int off = 16; off; off >>= 1) acc += __shfl_xor_sync(0xffffffffu, acc, off);
        if (threadIdx.x == 0) soff = acc;
    }
    __syncthreads();
    if (i < NN) {
        int r = g_rowptr[i] + soff;
        g_rowptr[i] = r;
        g_cursor[i] = r;
    }
    if (i == 0 && blockIdx.x == 0) g_rowptr[NN] = EE;
}
__global__ void k_fill(const int* __restrict__ ei) {
    int e = blockIdx.x * blockDim.x + threadIdx.x;
    if (e < EE) {
        int s  = ei[e];
        int dv = ei[EE + e];
        float w = g_dis[s] * g_dis[dv];
        int p = atomicAdd(&g_cursor[dv], 1);
        g_edge[p] = make_int2(s, __float_as_int(w));
    }
}

// ================= conversions / merged per-layer prep =================
__global__ void k_convX(const float* __restrict__ x) {
    int idx = blockIdx.x * blockDim.x + threadIdx.x;
    if (idx >= NN * 32) return;
    int i = idx >> 5, g = idx & 31;
    int k0 = g * 8;
    __half h[8];
    #pragma unroll
    for (int q = 0; q < 8; q++) {
        int k = k0 + q;
        float v = (k < 220) ? x[(size_t)i * 220 + k] : 0.f;
        h[q] = __float2half_rn(v);
    }
    *(uint4*)(g_actF + (size_t)i * 256 + k0) = *(uint4*)h;
}

__global__ void __launch_bounds__(256) k_prepLayer(
    const float* __restrict__ W, const float* __restrict__ gg, const float* __restrict__ bb,
    int K_, int N_, int KP, int useScale, int statIdx)
{
    __shared__ float s_scale[256], s_shift[256], s_red[256];
    int t = threadIdx.x;
    int n = blockIdx.x;

    float sc = 1.f, sh = 0.f;
    if (useScale && t < K_) {
        float m   = g_sumsA[statIdx][t] * (1.f / NN);
        float var = g_sumsqA[statIdx][t] * (1.f / NN) - m * m;
        float rs  = rsqrtf(var + EPSV);
        sc = rs * gg[t];
        sh = bb[t] - m * sc;
    }
    s_scale[t] = sc;
    s_shift[t] = sh;
    __syncthreads();

    for (int k = t; k < KP; k += 256) {
        float v = 0.f;
        if (n < N_ && k < K_) v = W[(size_t)k * N_ + n] * s_scale[k];
        __half hv = __float2half_rn(v);
        g_hB[(size_t)n * KP + k] = hv;
        g_lB[(size_t)n * KP + k] = __float2half_rn((v - __half2float(hv)) * LOSCALE);
    }

    if (useScale) {
        float part = 0.f;
        if (n < N_)
            for (int k = t; k < K_; k += 256) part += s_shift[k] * W[(size_t)k * N_ + n];
        s_red[t] = part;
        __syncthreads();
        #pragma unroll
        for (int off = 128; off > 0; off >>= 1) {
            if (t < off) s_red[t] += s_red[t + off];
            __syncthreads();
        }
        if (t == 0) g_cvec[n] = s_red[0];
    }
}

// ================= HMMA fp16 2-term split GEMM (A register double-buffer) ========
__device__ __forceinline__ void ldsm4(uint32_t& r0, uint32_t& r1, uint32_t& r2, uint32_t& r3,
                                      uint32_t addr) {
    asm volatile("ldmatrix.sync.aligned.m8n8.x4.shared.b16 {%0,%1,%2,%3}, [%4];"
        : "=r"(r0), "=r"(r1), "=r"(r2), "=r"(r3) : "r"(addr));
}
__device__ __forceinline__ void mma16816f(float* d, uint32_t a0, uint32_t a1, uint32_t a2,
                                          uint32_t a3, uint32_t b0, uint32_t b1) {
    asm volatile(
        "mma.sync.aligned.m16n8k16.row.col.f32.f16.f16.f32 "
        "{%0,%1,%2,%3}, {%4,%5,%6,%7}, {%8,%9}, {%0,%1,%2,%3};"
        : "+f"(d[0]), "+f"(d[1]), "+f"(d[2]), "+f"(d[3])
        : "r"(a0), "r"(a1), "r"(a2), "r"(a3), "r"(b0), "r"(b1));
}
#define SWZ(r, q) (((uint32_t)(r) << 7) + ((((uint32_t)(q)) ^ ((uint32_t)(r) & 7)) << 4))

template <int JM8>
__global__ void __launch_bounds__(256, 2) k_hgemm(int KP, int strideOut, int useCvec,
                                                  int colOff, int outHalf) {
    constexpr int TMAX  = JM8 / 2;
    constexpr int BROWS = JM8 * 8;
    __shared__ __half sA[128 * 64];
    __shared__ __half sBh[64 * 64];
    __shared__ __half sBl[64 * 64];

    int tid = threadIdx.x;
    int warp = tid >> 5, lane = tid & 31;
    int rowbase = blockIdx.y * 128;
    int colbase = colOff + blockIdx.x * 64;

    float accH[JM8][4], accL[JM8][4];
    #pragma unroll
    for (int j = 0; j < JM8; j++)
        #pragma unroll
        for (int q = 0; q < 4; q++) { accH[j][q] = 0.f; accL[j][q] = 0.f; }

    uint32_t sAB = smem_u32(sA);
    uint32_t sBhB = smem_u32(sBh), sBlB = smem_u32(sBl);

    int arow = warp * 16 + (lane & 15);
    int achk = lane >> 4;
    int brow = (lane & 7) + ((lane >> 4) << 3);
    int bchk = (lane >> 3) & 1;

    int aR[4], aQ;
    {
        aQ = tid & 7;
        #pragma unroll
        for (int it = 0; it < 4; it++) aR[it] = (tid + it * 256) >> 3;
    }
    bool rowOK[4];
    #pragma unroll
    for (int it = 0; it < 4; it++) rowOK[it] = (rowbase + aR[it]) < NN;

    int nchunks = KP >> 6;

    uint4 aReg[4];
    #pragma unroll
    for (int it = 0; it < 4; it++)
        aReg[it] = rowOK[it]
            ? *(const uint4*)(g_actF + (size_t)(rowbase + aR[it]) * KP + 0 + aQ * 8)
            : make_uint4(0u, 0u, 0u, 0u);

    for (int c = 0; c < nchunks; c++) {
        int k0 = c << 6;
        #pragma unroll
        for (int it = 0; it < 4; it++)
            *(uint4*)((char*)sA + SWZ(aR[it], aQ)) = aReg[it];
        #pragma unroll
        for (int it = 0; it < BROWS / 32; it++) {
            int u = tid + it * 256;
            int n = u >> 3, q = u & 7;
            size_t off = (size_t)(colbase + n) * KP + k0 + q * 8;
            uint32_t dz = SWZ(n, q);
            *(uint4*)((char*)sBh + dz) = *(const uint4*)(g_hB + off);
            *(uint4*)((char*)sBl + dz) = *(const uint4*)(g_lB + off);
        }
        __syncthreads();

        if (c + 1 < nchunks) {
            int k1 = (c + 1) << 6;
            #pragma unroll
            for (int it = 0; it < 4; it++)
                aReg[it] = rowOK[it]
                    ? *(const uint4*)(g_actF + (size_t)(rowbase + aR[it]) * KP + k1 + aQ * 8)
                    : make_uint4(0u, 0u, 0u, 0u);
        }

        #pragma unroll
        for (int s = 0; s < 4; s++) {
            int aq = s * 2 + achk;
            uint32_t ah0, ah1, ah2, ah3;
            ldsm4(ah0, ah1, ah2, ah3, sAB + SWZ(arow, aq));
            int bq = s * 2 + bchk;
            #pragma unroll
            for (int t = 0; t < TMAX; t++) {
                uint32_t bh[4], bl[4];
                uint32_t boff = SWZ(brow + t * 16, bq);
                ldsm4(bh[0], bh[1], bh[2], bh[3], sBhB + boff);
                ldsm4(bl[0], bl[1], bl[2], bl[3], sBlB + boff);
                #pragma unroll
                for (int jj = 0; jj < 2; jj++) {
                    int j = t * 2 + jj;
                    mma16816f(accH[j], ah0, ah1, ah2, ah3, bh[jj*2], bh[jj*2+1]);
                    mma16816f(accL[j], ah0, ah1, ah2, ah3, bl[jj*2], bl[jj*2+1]);
                }
            }
        }
        __syncthreads();
    }

    int r0 = rowbase + warp * 16 + (lane >> 2);
    int c00 = colbase + (lane & 3) * 2;
    #pragma unroll
    for (int j = 0; j < JM8; j++) {
        int col = c00 + j * 8;
        if (col >= strideOut) continue;
        float cv0 = useCvec ? g_cvec[col] : 0.f;
        float cv1 = useCvec ? g_cvec[col + 1] : 0.f;
        float v00 = accH[j][0] + accL[j][0] * INV_LOSCALE + cv0;
        float v01 = accH[j][1] + accL[j][1] * INV_LOSCALE + cv1;
        float v10 = accH[j][2] + accL[j][2] * INV_LOSCALE + cv0;
        float v11 = accH[j][3] + accL[j][3] * INV_LOSCALE + cv1;
        if (outHalf) {
            if (r0 < NN)
                *(__half2*)(g_bufH + (size_t)r0 * strideOut + col) = __floats2half2_rn(v00, v01);
            if (r0 + 8 < NN)
                *(__half2*)(g_bufH + (size_t)(r0 + 8) * strideOut + col) = __floats2half2_rn(v10, v11);
        } else {
            if (r0 < NN) {
                float* p = g_bufA + (size_t)r0 * strideOut + col;
                p[0] = v00; p[1] = v01;
            }
            if (r0 + 8 < NN) {
                float* p = g_bufA + (size_t)(r0 + 8) * strideOut + col;
                p[0] = v10; p[1] = v11;
            }
        }
    }
}

// ===== aggregation over fp16 h (layers 1-5): 2-deep gather prefetch, int2 edges =====
template <int EPG>
__global__ void __launch_bounds__(256) k_aggH(const float* __restrict__ bias,
                                              int d, int s8, int KPn, int statIdx)
{
    constexpr int G = 32 / EPG;
    int lane = threadIdx.x & 31;
    int warp = threadIdx.x >> 5;
    int sub  = lane & (G - 1);
    int grp  = lane / G;

    __shared__ float sh_sum[256], sh_sq[256], sh_bias[256];
    if (threadIdx.x < 256) {
        sh_sum[threadIdx.x] = 0.f;
        sh_sq[threadIdx.x] = 0.f;
        sh_bias[threadIdx.x] = (threadIdx.x < d) ? bias[threadIdx.x] : 0.f;
    }
    __syncthreads();

    float st_s[8], st_q[8];
    #pragma unroll
    for (int i = 0; i < 8; i++) { st_s[i] = 0.f; st_q[i] = 0.f; }

    const float4* __restrict__ H8 = (const float4*)g_bufH;
    bool lactive = (sub < s8);
    int nsg = KPn >> 3;
    const uint4 Z4 = make_uint4(0u, 0u, 0u, 0u);

    for (int node = blockIdx.x * 8 + warp; node < NN; node += gridDim.x * 8) {
        float acc8[8];
        #pragma unroll
        for (int i = 0; i < 8; i++) acc8[i] = 0.f;

        float dn = g_dis[node];
        if (grp == 0 && lactive) {
            float sw = dn * dn;
            uint4 u = *(const uint4*)(H8 + (size_t)node * s8 + sub);
            const __half2* h2 = (const __half2*)&u;
            #pragma unroll
            for (int i = 0; i < 4; i++) {
                float2 t = __half22float2(h2[i]);
                acc8[2*i]   = sw * t.x;
                acc8[2*i+1] = sw * t.y;
            }
        }

        int start = g_rowptr[node], end = g_rowptr[node + 1];
        for (int base = start; base < end; base += 32) {
            int e = base + lane;
            int ssrc = 0; float ww = 0.f;
            if (e < end) {
                int2 ed = g_edge[e];
                ssrc = ed.x;
                ww = __int_as_float(ed.y);
            }
            int cnt = min(32, end - base);
            int steps = (cnt + EPG - 1) / EPG;

            int   s2 = __shfl_sync(0xffffffffu, ssrc, grp);
            float w2 = __shfl_sync(0xffffffffu, ww,  grp);
            bool  vld = (grp < cnt) && lactive;
            uint4 v = vld ? *(const uint4*)(H8 + (size_t)s2 * s8 + sub) : Z4;

            for (int t = 0; t < steps; t++) {
                int ein = (t + 1) * EPG + grp;
                int   s2n = __shfl_sync(0xffffffffu, ssrc, ein & 31);
                float w2n = __shfl_sync(0xffffffffu, ww,  ein & 31);
                bool  vldn = (ein < cnt) && lactive;
                uint4 vn = vldn ? *(const uint4*)(H8 + (size_t)s2n * s8 + sub) : Z4;

                const __half2* h2 = (const __half2*)&v;
                #pragma unroll
                for (int i = 0; i < 4; i++) {
                    float2 tt = __half22float2(h2[i]);
                    acc8[2*i]   += w2 * tt.x;
                    acc8[2*i+1] += w2 * tt.y;
                }
                v = vn; w2 = w2n;
            }
        }

        if (EPG > 1) {
            #pragma unroll
            for (int off = G; off < 32; off <<= 1) {
                #pragma unroll
                for (int i = 0; i < 8; i++)
                    acc8[i] += __shfl_xor_sync(0xffffffffu, acc8[i], off);
            }
        }

        if (grp == 0) {
            for (int g = sub; g < nsg; g += G) {
                bool own = (g == sub);
                uint4 pf;
                __half* fp = (__half*)&pf;
                #pragma unroll
                for (int i = 0; i < 8; i++) {
                    int col = g * 8 + i;
                    float v2 = 0.f;
                    if (own && col < d) {
                        v2 = fmaxf(acc8[i] + sh_bias[col], 0.f);
                        st_s[i] += v2;
                        st_q[i] += v2 * v2;
                    }
                    fp[i] = __float2half_rn(v2);
                }
                *(uint4*)(g_actF + (size_t)node * KPn + g * 8) = pf;
            }
        }
    }

    __syncthreads();
    if (grp == 0 && lactive) {
        #pragma unroll
        for (int i = 0; i < 8; i++) {
            int col = sub * 8 + i;
            if (col < d) {
                atomicAdd(&sh_sum[col], st_s[i]);
                atomicAdd(&sh_sq[col],  st_q[i]);
            }
        }
    }
    __syncthreads();
    if (threadIdx.x < d) {
        atomicAdd(&g_sumsA[statIdx][threadIdx.x],  sh_sum[threadIdx.x]);
        atomicAdd(&g_sumsqA[statIdx][threadIdx.x], sh_sq[threadIdx.x]);
    }
}

// ===== final aggregation (layer 6): fp32 gather with 2-deep prefetch, log_softmax =====
__global__ void __launch_bounds__(256) k_aggLast(const float* __restrict__ bias,
                                                 float* __restrict__ outp, int d, int s4)
{
    constexpr int EPG = 4, G = 8;
    int lane = threadIdx.x & 31;
    int warp = threadIdx.x >> 5;
    int sub  = lane & (G - 1);
    int grp  = lane / G;

    const float4* __restrict__ H = (const float4*)g_bufA;
    bool lactive = (sub < s4);
    const float4 ZF = make_float4(0.f, 0.f, 0.f, 0.f);

    for (int node = blockIdx.x * 8 + warp; node < NN; node += gridDim.x * 8) {
        float4 acc = ZF;
        float dn = g_dis[node];
        if (grp == 0 && lactive) {
            float sw = dn * dn;
            float4 h = H[(size_t)node * s4 + sub];
            acc.x = sw * h.x; acc.y = sw * h.y; acc.z = sw * h.z; acc.w = sw * h.w;
        }

        int start = g_rowptr[node], end = g_rowptr[node + 1];
        for (int base = start; base < end; base += 32) {
            int e = base + lane;
            int ssrc = 0; float ww = 0.f;
            if (e < end) {
                int2 ed = g_edge[e];
                ssrc = ed.x;
                ww = __int_as_float(ed.y);
            }
            int cnt = min(32, end - base);
            int steps = (cnt + EPG - 1) / EPG;

            int e0 = grp;
            int   s2a = __shfl_sync(0xffffffffu, ssrc, e0 & 31);
            float w2a = __shfl_sync(0xffffffffu, ww,  e0 & 31);
            float4 v0 = ((e0 < cnt) && lactive) ? H[(size_t)s2a * s4 + sub] : ZF;

            for (int t = 0; t < steps; t++) {
                int ein = (t + 1) * EPG + grp;
                int   s2n = __shfl_sync(0xffffffffu, ssrc, ein & 31);
                float w2n = __shfl_sync(0xffffffffu, ww,  ein & 31);
                float4 vn = ((ein < cnt) && lactive) ? H[(size_t)s2n * s4 + sub] : ZF;

                acc.x += w2a * v0.x; acc.y += w2a * v0.y;
                acc.z += w2a * v0.z; acc.w += w2a * v0.w;
                v0 = vn; w2a = w2n;
            }
        }

        #pragma unroll
        for (int off = G; off < 32; off <<= 1) {
            acc.x += __shfl_xor_sync(0xffffffffu, acc.x, off);
            acc.y += __shfl_xor_sync(0xffffffffu, acc.y, off);
            acc.z += __shfl_xor_sync(0xffffffffu, acc.z, off);
            acc.w += __shfl_xor_sync(0xffffffffu, acc.w, off);
        }

        float vals[4] = {acc.x, acc.y, acc.z, acc.w};
        float lmax = -INFINITY;
        #pragma unroll
        for (int q = 0; q < 4; q++) {
            int col = sub * 4 + q;
            float v = (grp == 0 && col < d) ? vals[q] + bias[col] : -INFINITY;
            vals[q] = v;
            lmax = fmaxf(lmax, v);
        }
        #pragma unroll
        for (int off = 1; off < G; off <<= 1)
            lmax = fmaxf(lmax, __shfl_xor_sync(0xffffffffu, lmax, off));
        float lsum = 0.f;
        #pragma unroll
        for (int q = 0; q < 4; q++) {
            int col = sub * 4 + q;
            if (grp == 0 && col < d) lsum += expf(vals[q] - lmax);
        }
        #pragma unroll
        for (int off = 1; off < G; off <<= 1)
            lsum += __shfl_xor_sync(0xffffffffu, lsum, off);
        float lse = logf(lsum) + lmax;
        if (grp == 0) {
            #pragma unroll
            for (int q = 0; q < 4; q++) {
                int col = sub * 4 + q;
                if (col < d) outp[(size_t)node * d + col] = vals[q] - lse;
            }
        }
    }
}

// ================= launch =================
extern "C" void kernel_launch(void* const* d_in, const int* in_sizes, int n_in,
                              void* d_out, int out_size) {
    const float* x  = (const float*)d_in[0];
    const int*   ei = (const int*)d_in[1];
    static const int DIMS_[7]  = {220, 220, 150, 100, 60, 30, 17};
    static const int KPt[6]    = {256, 256, 192, 128, 64, 64};
    static const int NPADc[6]  = {224, 160, 128, 64, 32, 32};
    static const int STRIDEo[6]= {224, 152, 104, 64, 32, 20};
    const float* W[6]; const float* b[6];
    for (int i = 0; i < 6; i++) {
        W[i] = (const float*)d_in[2 + 2 * i];
        b[i] = (const float*)d_in[3 + 2 * i];
    }
    const float* gpar[5]; const float* bpar[5];
    for (int i = 0; i < 5; i++) {
        gpar[i] = (const float*)d_in[14 + 2 * i];
        bpar[i] = (const float*)d_in[15 + 2 * i];
    }

    // preprocessing
    k_zero<<<(NN + 255) / 256, 256>>>();
    k_hist<<<(EE + 255) / 256, 256>>>(ei + EE);
    int nb = (NN + 511) / 512;
    k_scan1<<<nb, 512>>>();
    k_scan3<<<nb, 512>>>();
    k_fill<<<(EE + 255) / 256, 256>>>(ei);
    k_convX<<<(NN * 32 + 255) / 256, 256>>>(x);

    const int AGG_GRID = 1184;
    const int ROW_BLKS = (NN + 127) / 128;

    for (int L = 0; L < 6; L++) {
        int K_ = DIMS_[L], Nc = DIMS_[L + 1];
        int KP = KPt[L], Npad = NPADc[L], so = STRIDEo[L];
        int outHalf = (L < 5) ? 1 : 0;
        int uc = L > 0 ? 1 : 0;

        k_prepLayer<<<Npad, 256>>>(W[L],
                                   L > 0 ? gpar[L - 1] : nullptr,
                                   L > 0 ? bpar[L - 1] : nullptr,
                                   K_, Nc, KP, uc, L > 0 ? L - 1 : 0);

        int nfull = Npad / 64;
        int tail  = Npad - nfull * 64;
        if (nfull > 0) {
            dim3 gg(nfull, ROW_BLKS);
            k_hgemm<8><<<gg, 256>>>(KP, so, uc, 0, outHalf);
        }
        if (tail > 0) {
            dim3 gg(1, ROW_BLKS);
            k_hgemm<4><<<gg, 256>>>(KP, so, uc, nfull * 64, outHalf);
        }

        if (L < 5) {
            int s8 = so / 8;                 // 28, 19, 13, 8, 4
            int KPn = KPt[L + 1];
            if (L <= 1)      k_aggH<1><<<AGG_GRID, 256>>>(b[L], Nc, s8, KPn, L);
            else if (L == 2) k_aggH<2><<<AGG_GRID, 256>>>(b[L], Nc, s8, KPn, L);
            else if (L == 3) k_aggH<4><<<AGG_GRID, 256>>>(b[L], Nc, s8, KPn, L);
            else             k_aggH<8><<<AGG_GRID, 256>>>(b[L], Nc, s8, KPn, L);
        } else {
            k_aggLast<<<AGG_GRID, 256>>>(b[L], (float*)d_out, Nc, so / 4);
        }
    }
}